// round 1
// baseline (speedup 1.0000x reference)
#include <cuda_runtime.h>
#include <stdint.h>

#define BATCH    8
#define NATOMS   256
#define ASIZE    1024
#define NSAMP    32768
#define TOKEEP   256
#define PERB     (NATOMS * NSAMP)      /* 8,388,608 elements per batch */
#define NBUCK    8192                  /* 13-bit coarse buckets */
#define CAP      4096                  /* candidate capacity per batch */

// ---------------- device scratch (no allocations allowed) ----------------
__device__ unsigned g_hist[BATCH][NBUCK];
__device__ int      g_candCount[BATCH];
__device__ unsigned g_candKey[BATCH][CAP];   // order-mapped bits
__device__ int      g_candIdx[BATCH][CAP];   // flat index within batch
__device__ unsigned g_thresh[BATCH];
__device__ float    g_selVal[BATCH][TOKEEP];
__device__ int      g_selIdx[BATCH][TOKEEP];

// order-preserving float -> uint map (larger float => larger uint)
__device__ __forceinline__ unsigned mapf(float f) {
    unsigned u = __float_as_uint(f);
    return u ^ ((u >> 31) ? 0xFFFFFFFFu : 0x80000000u);
}
__device__ __forceinline__ float unmapf(unsigned u) {
    unsigned b = (u & 0x80000000u) ? (u ^ 0x80000000u) : ~u;
    return __uint_as_float(b);
}

// ---------------- kernel 0: zero the global histograms ----------------
__global__ void zero_hist_kernel() {
    int i = blockIdx.x * blockDim.x + threadIdx.x;
    if (i < BATCH * NBUCK) ((unsigned*)g_hist)[i] = 0u;
}

// ---------------- kernel 1: per-batch 13-bit histogram ----------------
__global__ void hist_kernel(const float* __restrict__ x) {
    __shared__ unsigned sh[NBUCK];
    const int b = blockIdx.y;
    for (int i = threadIdx.x; i < NBUCK; i += blockDim.x) sh[i] = 0u;
    __syncthreads();

    const float4* xb = (const float4*)(x + (size_t)b * PERB);
    const int nvec = PERB / 4;
    for (int i = blockIdx.x * blockDim.x + threadIdx.x; i < nvec;
         i += gridDim.x * blockDim.x) {
        float4 v = xb[i];
        atomicAdd(&sh[mapf(v.x) >> 19], 1u);
        atomicAdd(&sh[mapf(v.y) >> 19], 1u);
        atomicAdd(&sh[mapf(v.z) >> 19], 1u);
        atomicAdd(&sh[mapf(v.w) >> 19], 1u);
    }
    __syncthreads();
    for (int i = threadIdx.x; i < NBUCK; i += blockDim.x) {
        unsigned c = sh[i];
        if (c) atomicAdd(&g_hist[b][i], c);
    }
}

// ---------------- kernel 2: find per-batch threshold bucket ----------------
__global__ void thresh_kernel() {
    int b = threadIdx.x;
    if (b >= BATCH) return;
    unsigned cum = 0;
    unsigned t = 0;
    for (int i = NBUCK - 1; i >= 0; --i) {
        cum += g_hist[b][i];
        if (cum >= TOKEEP) { t = (unsigned)i; break; }
    }
    g_thresh[b] = t;
    g_candCount[b] = 0;   // reset before collection pass
}

// ---------------- kernel 3: collect candidates >= threshold bucket ----------------
__global__ void collect_kernel(const float* __restrict__ x) {
    const int b = blockIdx.y;
    const unsigned t = g_thresh[b];
    const float4* xb = (const float4*)(x + (size_t)b * PERB);
    const int nvec = PERB / 4;
    for (int i = blockIdx.x * blockDim.x + threadIdx.x; i < nvec;
         i += gridDim.x * blockDim.x) {
        float4 v = xb[i];
        float vals[4] = {v.x, v.y, v.z, v.w};
#pragma unroll
        for (int j = 0; j < 4; ++j) {
            unsigned u = mapf(vals[j]);
            if ((u >> 19) >= t) {
                int p = atomicAdd(&g_candCount[b], 1);
                if (p < CAP) {
                    g_candKey[b][p] = u;
                    g_candIdx[b][p] = i * 4 + j;
                }
            }
        }
    }
}

// ---------------- kernel 4: exact top-256 among candidates ----------------
// One block per batch. O(n^2) rank with tie-break by lower index
// (matches lax.top_k: descending values, lower index wins ties).
__global__ void select_kernel() {
    __shared__ unsigned su[CAP];
    __shared__ int      sidx[CAP];
    const int b = blockIdx.x;
    int n = g_candCount[b];
    if (n > CAP) n = CAP;

    for (int i = threadIdx.x; i < n; i += blockDim.x) {
        su[i]   = g_candKey[b][i];
        sidx[i] = g_candIdx[b][i];
    }
    // pre-clear selection slots (handles pathological n < TOKEEP safely: value 0)
    for (int i = threadIdx.x; i < TOKEEP; i += blockDim.x) {
        g_selVal[b][i] = 0.0f;
        g_selIdx[b][i] = 0;
    }
    __syncthreads();

    for (int i = threadIdx.x; i < n; i += blockDim.x) {
        unsigned ui = su[i];
        int      xi = sidx[i];
        int rank = 0;
        for (int j = 0; j < n; ++j) {
            unsigned uj = su[j];
            rank += (uj > ui) || (uj == ui && sidx[j] < xi);
        }
        if (rank < TOKEEP) {
            g_selVal[b][rank] = unmapf(ui);
            g_selIdx[b][rank] = xi;
        }
    }
}

// ---------------- kernel 5: scatter-add contributions ----------------
// grid (TOKEEP, BATCH); each block adds v * atom_row into out[b].
__global__ void scatter_kernel(const float* __restrict__ atoms,
                               float* __restrict__ out) {
    const int b = blockIdx.y;
    const int k = blockIdx.x;
    const float v = g_selVal[b][k];
    const int idx = g_selIdx[b][k];
    const int aidx = idx / NSAMP;
    const int s    = idx % NSAMP;
    const float* __restrict__ arow = atoms + (size_t)aidx * ASIZE;
    float* __restrict__ ob = out + (size_t)b * NSAMP;

    for (int j = threadIdx.x; j < ASIZE; j += blockDim.x) {
        int p = s + j;
        if (p < NSAMP) atomicAdd(&ob[p], v * arow[j]);
    }
}

// ---------------- launch ----------------
extern "C" void kernel_launch(void* const* d_in, const int* in_sizes, int n_in,
                              void* d_out, int out_size) {
    const float* x     = (const float*)d_in[0];   // [8, 256*32768] f32
    const float* atoms = (const float*)d_in[1];   // [1, 256, 1024] f32
    float* out = (float*)d_out;                   // [8, 1, 32768] f32

    (void)in_sizes; (void)n_in;

    // zero output (poisoned by harness) — async, capturable
    cudaMemsetAsync(out, 0, (size_t)out_size * sizeof(float));

    zero_hist_kernel<<<(BATCH * NBUCK + 255) / 256, 256>>>();

    dim3 hgrid(512, BATCH);
    hist_kernel<<<hgrid, 256>>>(x);

    thresh_kernel<<<1, 32>>>();

    dim3 cgrid(512, BATCH);
    collect_kernel<<<cgrid, 256>>>(x);

    select_kernel<<<BATCH, 256>>>();

    dim3 sgrid(TOKEEP, BATCH);
    scatter_kernel<<<sgrid, 256>>>(atoms, out);
}

// round 3
// speedup vs baseline: 1.8961x; 1.8961x over previous
#include <cuda_runtime.h>
#include <stdint.h>

#define BATCH    8
#define NATOMS   256
#define ASIZE    1024
#define NSAMP    32768
#define TOKEEP   256
#define PERB     (NATOMS * NSAMP)      /* 8,388,608 elements per batch */
#define NBUCK    8192                  /* 13-bit coarse buckets (fallback only) */
#define CAP      16384                 /* candidate capacity per batch */
#define SHCAP    4096                  /* shared-memory fast path for select */
#define SPEC_T   3.5f                  /* speculative threshold (~1950 hits/batch for N(0,1)) */

// ---------------- device scratch (no allocations allowed) ----------------
__device__ unsigned g_hist[BATCH][NBUCK];
__device__ int      g_candCount[BATCH];
__device__ unsigned g_candKey[BATCH][CAP];   // order-mapped bits
__device__ int      g_candIdx[BATCH][CAP];   // flat index within batch
__device__ unsigned g_thresh[BATCH];
__device__ int      g_fallback;              // 1 => speculation failed for some batch
__device__ float    g_selVal[BATCH][TOKEEP];
__device__ int      g_selIdx[BATCH][TOKEEP];

// order-preserving float -> uint map (larger float => larger uint)
__device__ __forceinline__ unsigned mapf(float f) {
    unsigned u = __float_as_uint(f);
    return u ^ ((u >> 31) ? 0xFFFFFFFFu : 0x80000000u);
}
__device__ __forceinline__ float unmapf(unsigned u) {
    unsigned b = (u & 0x80000000u) ? (u ^ 0x80000000u) : ~u;
    return __uint_as_float(b);
}

// ---------------- kernel: reset counters + flag ----------------
__global__ void reset_kernel() {
    int i = threadIdx.x;
    if (i < BATCH) g_candCount[i] = 0;
    if (i == 0) g_fallback = 0;
}

// ---------------- kernel: speculative single-pass collect ----------------
__global__ void collect_spec_kernel(const float* __restrict__ x) {
    const int b = blockIdx.y;
    const float4* __restrict__ xb = (const float4*)(x + (size_t)b * PERB);
    const int nvec = PERB / 4;
    const int stride = gridDim.x * blockDim.x;
    for (int i = blockIdx.x * blockDim.x + threadIdx.x; i < nvec; i += stride) {
        float4 v = xb[i];
        float m = fmaxf(fmaxf(v.x, v.y), fmaxf(v.z, v.w));
        if (m >= SPEC_T) {
            float vals[4] = {v.x, v.y, v.z, v.w};
#pragma unroll
            for (int j = 0; j < 4; ++j) {
                if (vals[j] >= SPEC_T) {
                    int p = atomicAdd(&g_candCount[b], 1);
                    if (p < CAP) {
                        g_candKey[b][p] = mapf(vals[j]);
                        g_candIdx[b][p] = i * 4 + j;
                    }
                }
            }
        }
    }
}

// ---------------- kernel: check speculation ----------------
__global__ void check_kernel() {
    int b = threadIdx.x;
    if (b >= BATCH) return;
    int c = g_candCount[b];
    if (c < TOKEEP || c > CAP) atomicExch(&g_fallback, 1);
}

// ======================= fallback path (flag-predicated) =======================

__global__ void zero_hist_kernel() {
    if (!g_fallback) return;
    int i = blockIdx.x * blockDim.x + threadIdx.x;
    if (i < BATCH * NBUCK) ((unsigned*)g_hist)[i] = 0u;
}

__global__ void hist_kernel(const float* __restrict__ x) {
    if (!g_fallback) return;
    __shared__ unsigned sh[NBUCK];
    const int b = blockIdx.y;
    for (int i = threadIdx.x; i < NBUCK; i += blockDim.x) sh[i] = 0u;
    __syncthreads();

    const float4* xb = (const float4*)(x + (size_t)b * PERB);
    const int nvec = PERB / 4;
    for (int i = blockIdx.x * blockDim.x + threadIdx.x; i < nvec;
         i += gridDim.x * blockDim.x) {
        float4 v = xb[i];
        atomicAdd(&sh[mapf(v.x) >> 19], 1u);
        atomicAdd(&sh[mapf(v.y) >> 19], 1u);
        atomicAdd(&sh[mapf(v.z) >> 19], 1u);
        atomicAdd(&sh[mapf(v.w) >> 19], 1u);
    }
    __syncthreads();
    for (int i = threadIdx.x; i < NBUCK; i += blockDim.x) {
        unsigned c = sh[i];
        if (c) atomicAdd(&g_hist[b][i], c);
    }
}

__global__ void thresh_kernel() {
    if (!g_fallback) return;
    int b = threadIdx.x;
    if (b >= BATCH) return;
    unsigned cum = 0;
    unsigned t = 0;
    for (int i = NBUCK - 1; i >= 0; --i) {
        cum += g_hist[b][i];
        if (cum >= TOKEEP) { t = (unsigned)i; break; }
    }
    g_thresh[b] = t;
    g_candCount[b] = 0;   // reset before fallback collection
}

__global__ void collect_fb_kernel(const float* __restrict__ x) {
    if (!g_fallback) return;
    const int b = blockIdx.y;
    const unsigned t = g_thresh[b];
    const float4* xb = (const float4*)(x + (size_t)b * PERB);
    const int nvec = PERB / 4;
    for (int i = blockIdx.x * blockDim.x + threadIdx.x; i < nvec;
         i += gridDim.x * blockDim.x) {
        float4 v = xb[i];
        float vals[4] = {v.x, v.y, v.z, v.w};
#pragma unroll
        for (int j = 0; j < 4; ++j) {
            unsigned u = mapf(vals[j]);
            if ((u >> 19) >= t) {
                int p = atomicAdd(&g_candCount[b], 1);
                if (p < CAP) {
                    g_candKey[b][p] = u;
                    g_candIdx[b][p] = i * 4 + j;
                }
            }
        }
    }
}

// ======================= selection + scatter =======================

// One block per batch, 1024 threads. Exact top-256 by rank.
// Packed 64-bit compare: c = (key << 32) | (idx ^ 0xFFFFFFFF)
// => bigger key wins; equal key: smaller idx => bigger packed => earlier rank.
__global__ void select_kernel() {
    __shared__ unsigned long long sc[SHCAP];
    const int b = blockIdx.x;
    int n = g_candCount[b];
    if (n > CAP) n = CAP;

    // pre-clear selection slots
    for (int i = threadIdx.x; i < TOKEEP; i += blockDim.x) {
        g_selVal[b][i] = 0.0f;
        g_selIdx[b][i] = 0;
    }

    if (n <= SHCAP) {
        for (int i = threadIdx.x; i < n; i += blockDim.x) {
            sc[i] = ((unsigned long long)g_candKey[b][i] << 32)
                  | (unsigned)(g_candIdx[b][i] ^ 0xFFFFFFFF);
        }
        __syncthreads();
        for (int i = threadIdx.x; i < n; i += blockDim.x) {
            unsigned long long ci = sc[i];
            int rank = 0;
            for (int j = 0; j < n; ++j) rank += (sc[j] > ci);
            if (rank < TOKEEP) {
                g_selVal[b][rank] = unmapf((unsigned)(ci >> 32));
                g_selIdx[b][rank] = (int)((unsigned)ci ^ 0xFFFFFFFF);
            }
        }
    } else {
        // slow path: global reads (L1/L2 resident)
        __syncthreads();
        for (int i = threadIdx.x; i < n; i += blockDim.x) {
            unsigned long long ci = ((unsigned long long)g_candKey[b][i] << 32)
                                  | (unsigned)(g_candIdx[b][i] ^ 0xFFFFFFFF);
            int rank = 0;
            for (int j = 0; j < n; ++j) {
                unsigned long long cj = ((unsigned long long)g_candKey[b][j] << 32)
                                      | (unsigned)(g_candIdx[b][j] ^ 0xFFFFFFFF);
                rank += (cj > ci);
            }
            if (rank < TOKEEP) {
                g_selVal[b][rank] = unmapf((unsigned)(ci >> 32));
                g_selIdx[b][rank] = (int)((unsigned)ci ^ 0xFFFFFFFF);
            }
        }
    }
}

// grid (TOKEEP, BATCH); each block adds v * atom_row into out[b].
__global__ void scatter_kernel(const float* __restrict__ atoms,
                               float* __restrict__ out) {
    const int b = blockIdx.y;
    const int k = blockIdx.x;
    const float v = g_selVal[b][k];
    const int idx = g_selIdx[b][k];
    const int aidx = idx / NSAMP;
    const int s    = idx % NSAMP;
    const float* __restrict__ arow = atoms + (size_t)aidx * ASIZE;
    float* __restrict__ ob = out + (size_t)b * NSAMP;

    for (int j = threadIdx.x; j < ASIZE; j += blockDim.x) {
        int p = s + j;
        if (p < NSAMP) atomicAdd(&ob[p], v * arow[j]);
    }
}

// ---------------- launch ----------------
extern "C" void kernel_launch(void* const* d_in, const int* in_sizes, int n_in,
                              void* d_out, int out_size) {
    const float* x     = (const float*)d_in[0];   // [8, 256*32768] f32
    const float* atoms = (const float*)d_in[1];   // [1, 256, 1024] f32
    float* out = (float*)d_out;                   // [8, 1, 32768] f32
    (void)in_sizes; (void)n_in;

    cudaMemsetAsync(out, 0, (size_t)out_size * sizeof(float));

    reset_kernel<<<1, 32>>>();

    dim3 cgrid(2048, BATCH);
    collect_spec_kernel<<<cgrid, 256>>>(x);

    check_kernel<<<1, 32>>>();

    // fallback chain (no-ops when speculation succeeded)
    zero_hist_kernel<<<(BATCH * NBUCK + 255) / 256, 256>>>();
    dim3 hgrid(256, BATCH);
    hist_kernel<<<hgrid, 256>>>(x);
    thresh_kernel<<<1, 32>>>();
    dim3 fgrid(512, BATCH);
    collect_fb_kernel<<<fgrid, 256>>>(x);

    select_kernel<<<BATCH, 1024>>>();

    dim3 sgrid(TOKEEP, BATCH);
    scatter_kernel<<<sgrid, 256>>>(atoms, out);
}